// round 1
// baseline (speedup 1.0000x reference)
#include <cuda_runtime.h>
#include <math.h>

// ---------------- problem constants (fixed by setup_inputs) ----------------
#define NB     32     // batch
#define C_IN   64     // input channels
#define HW     128    // spatial H = W
#define OCH    256    // output channels
#define HASH   8      // num hashes
#define D_A    603    // (64+3)*9
#define KW2    576    // 64*9
#define MPOW   27     // appended power dims (3*9)
#define TSZ    512    // table size
#define RADIUS 4.0f
#define UBND   0.99f

// ---------------- device scratch (no allocations allowed) ------------------
__device__ int   g_hist[HASH * TSZ];
__device__ float g_norm[OCH];
__device__ float g_scale;
__device__ int   g_kbuckets[HASH * OCH];
__device__ int   g_voted[HASH];
__device__ int   g_mask[OCH];

// ---------------- 0: zero the global histogram -----------------------------
__global__ void zero_hist_kernel() {
    int i = blockIdx.x * blockDim.x + threadIdx.x;
    if (i < HASH * TSZ) g_hist[i] = 0;
}

// ---------------- 1: kernel-row norms + global scale ------------------------
__global__ void norms_kernel(const float* __restrict__ w) {
    __shared__ float sn[256];
    int o = threadIdx.x;             // 256 threads == 256 kernel rows
    const float* row = w + o * KW2;
    float s = 0.f;
    for (int j = 0; j < KW2; j++) { float v = row[j]; s += v * v; }
    float nrm = sqrtf(s);
    g_norm[o] = nrm;
    sn[o] = nrm;
    __syncthreads();
    for (int st = 128; st > 0; st >>= 1) {
        if (o < st) sn[o] = fmaxf(sn[o], sn[o + st]);
        __syncthreads();
    }
    if (o == 0) g_scale = UBND / sn[0];
}

// ---------------- 2: bucket id of every kernel under every hash -------------
// one warp per (h, o) pair; 2048 warps total
__global__ void kbuckets_kernel(const float* __restrict__ w,
                                const float* __restrict__ a,
                                const float* __restrict__ b) {
    int wid  = (blockIdx.x * blockDim.x + threadIdx.x) >> 5;
    int lane = threadIdx.x & 31;
    if (wid >= HASH * OCH) return;
    int h = wid >> 8;        // /256
    int o = wid & 255;

    const float* ar = a + h * D_A;
    const float* wr = w + o * KW2;
    float s = 0.f;
    for (int j = lane; j < KW2; j += 32) s += ar[j] * wr[j];
    #pragma unroll
    for (int off = 16; off; off >>= 1) s += __shfl_down_sync(0xffffffffu, s, off);

    if (lane == 0) {
        float dot = g_scale * s;                 // a_flat . scaled_row
        float t = g_scale * g_norm[o];           // sn
        #pragma unroll 1
        for (int p = 0; p < MPOW; p++) {         // sn^(2^1) ... sn^(2^27)
            t = t * t;
            dot += ar[KW2 + p] * t;
        }
        float v  = floorf((dot + b[h]) / RADIUS);
        int   bk = (int)fabsf(fmodf(v, (float)TSZ));
        g_kbuckets[h * OCH + o] = bk;
    }
}

// ---------------- 3: vote — hash conv of padded input + histogram -----------
// tile 32x32 output px; 256 threads; each thread: 4 px (column of 4 rows),
// all 8 hash accumulators in registers.
#define VT 32
__global__ void vote_kernel(const float* __restrict__ x,
                            const float* __restrict__ a,
                            const float* __restrict__ b) {
    __shared__ float xs[4][VT + 2][36];       // 4-ch chunk, padded input tile
    __shared__ float ws[4][9][HASH];          // hash weights for this chunk
    __shared__ float sb[HASH];
    __shared__ int   shist[HASH * TSZ];

    int tid = threadIdx.x;
    int n   = blockIdx.z;
    int x0  = blockIdx.x * VT;
    int y0  = blockIdx.y * VT;

    for (int e = tid; e < HASH * TSZ; e += 256) shist[e] = 0;
    if (tid < HASH) sb[tid] = b[tid];

    int col = tid & 31;
    int rb  = (tid >> 5) << 2;

    float acc[HASH][4];
    #pragma unroll
    for (int h = 0; h < HASH; h++)
        #pragma unroll
        for (int p = 0; p < 4; p++) acc[h][p] = 0.f;

    // 67 channels (last 3 are constant 0.5 inside the image, 0 in padding),
    // processed as 17 chunks of 4 (68th channel is zero-padded).
    for (int c0 = 0; c0 < 68; c0 += 4) {
        __syncthreads();
        for (int e = tid; e < 4 * 34 * 34; e += 256) {
            int c   = e / (34 * 34);
            int rem = e % (34 * 34);
            int ry = rem / 34, rx = rem % 34;
            int cg = c0 + c;
            int gy = y0 - 1 + ry, gx = x0 - 1 + rx;
            float v = 0.f;
            if (cg < 67 && gy >= 0 && gy < HW && gx >= 0 && gx < HW)
                v = (cg < C_IN) ? x[((n * C_IN + cg) * HW + gy) * HW + gx] : 0.5f;
            xs[c][ry][rx] = v;
        }
        for (int e = tid; e < 4 * 9 * HASH; e += 256) {
            int h   = e % HASH;
            int rem = e / HASH;
            int c = rem / 9, khw = rem % 9;
            int cg = c0 + c;
            ws[c][khw][h] = (cg < 67) ? a[h * D_A + cg * 9 + khw] : 0.f;
        }
        __syncthreads();

        #pragma unroll
        for (int c = 0; c < 4; c++) {
            #pragma unroll
            for (int kh = 0; kh < 3; kh++) {
                #pragma unroll
                for (int kw = 0; kw < 3; kw++) {
                    float wv[HASH];
                    #pragma unroll
                    for (int h = 0; h < HASH; h++) wv[h] = ws[c][kh * 3 + kw][h];
                    float xv[4];
                    #pragma unroll
                    for (int p = 0; p < 4; p++) xv[p] = xs[c][rb + p + kh][col + kw];
                    #pragma unroll
                    for (int h = 0; h < HASH; h++)
                        #pragma unroll
                        for (int p = 0; p < 4; p++) acc[h][p] += wv[h] * xv[p];
                }
            }
        }
    }
    __syncthreads();

    #pragma unroll
    for (int h = 0; h < HASH; h++) {
        #pragma unroll
        for (int p = 0; p < 4; p++) {
            float v  = floorf((acc[h][p] + sb[h]) / RADIUS);
            int   bk = (int)fabsf(fmodf(v, (float)TSZ));
            atomicAdd(&shist[h * TSZ + bk], 1);
        }
    }
    __syncthreads();
    for (int e = tid; e < HASH * TSZ; e += 256) {
        int v = shist[e];
        if (v) atomicAdd(&g_hist[e], v);
    }
}

// ---------------- 4: argmax per hash (ties -> lowest index, like jnp) -------
__global__ void argmax_kernel() {
    int w    = threadIdx.x >> 5;   // 8 warps, one per hash
    int lane = threadIdx.x & 31;
    int best = -1, bidx = 0;
    for (int j = lane; j < TSZ; j += 32) {
        int c = g_hist[w * TSZ + j];
        if (c > best) { best = c; bidx = j; }   // strict > keeps lowest j
    }
    #pragma unroll
    for (int off = 16; off; off >>= 1) {
        int ob = __shfl_down_sync(0xffffffffu, best, off);
        int oi = __shfl_down_sync(0xffffffffu, bidx, off);
        if (ob > best || (ob == best && oi < bidx)) { best = ob; bidx = oi; }
    }
    if (lane == 0) g_voted[w] = bidx;
}

// ---------------- 5: active-channel mask -------------------------------------
__global__ void mask_kernel() {
    __shared__ int sv[HASH];
    if (threadIdx.x < HASH) sv[threadIdx.x] = g_voted[threadIdx.x];
    __syncthreads();
    int o = threadIdx.x;
    int m = 0;
    #pragma unroll
    for (int h = 0; h < HASH; h++) {
        int kb = g_kbuckets[h * OCH + o];
        #pragma unroll
        for (int j = 0; j < HASH; j++) m |= (kb == sv[j]);
    }
    g_mask[o] = m;
}

// ---------------- 6: main conv (FFMA-bound direct conv) ----------------------
// block: 16x16 px tile x 32 output channels; 256 threads.
// thread: 8 oc x 4 px (column) = 32 accumulators.
#define CT 16
__global__ void conv_kernel(const float* __restrict__ x,
                            const float* __restrict__ w,
                            float* __restrict__ out) {
    __shared__ float xs[8][CT + 2][20];   // row stride 20 -> conflict-free
    __shared__ float ws[8][9][32];
    __shared__ float smask[32];

    int tid = threadIdx.x;
    int z   = blockIdx.z;
    int ocg = z & 7;
    int n   = z >> 3;
    int ocbase = ocg * 32;
    int x0 = blockIdx.x * CT, y0 = blockIdx.y * CT;

    if (tid < 32) smask[tid] = g_mask[ocbase + tid] ? 1.f : 0.f;
    __syncthreads();

    bool any = false;
    #pragma unroll
    for (int i = 0; i < 32; i++) any |= (smask[i] != 0.f);

    int ocsub = tid >> 6;         // 0..3  -> oc group of 8
    int pxg   = tid & 63;
    int col   = pxg & 15;         // 0..15
    int rb    = (pxg >> 4) << 2;  // 0,4,8,12

    if (!any) {                   // whole oc-group inactive: exact zeros
        #pragma unroll
        for (int i = 0; i < 8; i++) {
            int oc = ocbase + ocsub * 8 + i;
            #pragma unroll
            for (int p = 0; p < 4; p++)
                out[((n * OCH + oc) * HW + y0 + rb + p) * HW + x0 + col] = 0.f;
        }
        return;
    }

    float acc[8][4];
    #pragma unroll
    for (int i = 0; i < 8; i++)
        #pragma unroll
        for (int p = 0; p < 4; p++) acc[i][p] = 0.f;

    for (int c0 = 0; c0 < C_IN; c0 += 8) {
        __syncthreads();
        for (int e = tid; e < 8 * 18 * 18; e += 256) {
            int c   = e / 324;
            int rem = e % 324;
            int ry = rem / 18, rx = rem % 18;
            int gy = y0 - 1 + ry, gx = x0 - 1 + rx;
            float v = 0.f;
            if (gy >= 0 && gy < HW && gx >= 0 && gx < HW)
                v = x[((n * C_IN + c0 + c) * HW + gy) * HW + gx];
            xs[c][ry][rx] = v;
        }
        for (int e = tid; e < 8 * 9 * 32; e += 256) {
            int oc  = e / 72;
            int rem = e % 72;
            int c = rem / 9, khw = rem % 9;
            ws[c][khw][oc] = w[(ocbase + oc) * KW2 + (c0 + c) * 9 + khw];
        }
        __syncthreads();

        #pragma unroll 2
        for (int c = 0; c < 8; c++) {
            #pragma unroll
            for (int kh = 0; kh < 3; kh++) {
                #pragma unroll
                for (int kw = 0; kw < 3; kw++) {
                    float wv[8];
                    #pragma unroll
                    for (int i = 0; i < 8; i++) wv[i] = ws[c][kh * 3 + kw][ocsub * 8 + i];
                    float xv[4];
                    #pragma unroll
                    for (int p = 0; p < 4; p++) xv[p] = xs[c][rb + p + kh][col + kw];
                    #pragma unroll
                    for (int i = 0; i < 8; i++)
                        #pragma unroll
                        for (int p = 0; p < 4; p++) acc[i][p] += wv[i] * xv[p];
                }
            }
        }
    }

    #pragma unroll
    for (int i = 0; i < 8; i++) {
        float m  = smask[ocsub * 8 + i];
        int   oc = ocbase + ocsub * 8 + i;
        #pragma unroll
        for (int p = 0; p < 4; p++)
            out[((n * OCH + oc) * HW + y0 + rb + p) * HW + x0 + col] = acc[i][p] * m;
    }
}

// ---------------- launch ------------------------------------------------------
extern "C" void kernel_launch(void* const* d_in, const int* in_sizes, int n_in,
                              void* d_out, int out_size) {
    const float* x = (const float*)d_in[0];   // [32,64,128,128]
    const float* w = (const float*)d_in[1];   // [256,64,3,3]
    const float* a = (const float*)d_in[2];   // [8,67,3,3]
    const float* b = (const float*)d_in[3];   // [8]
    float* out = (float*)d_out;               // [32,256,128,128]

    zero_hist_kernel<<<16, 256>>>();
    norms_kernel<<<1, 256>>>(w);
    kbuckets_kernel<<<256, 256>>>(w, a, b);
    vote_kernel<<<dim3(4, 4, NB), 256>>>(x, a, b);
    argmax_kernel<<<1, 256>>>();
    mask_kernel<<<1, 256>>>();
    conv_kernel<<<dim3(HW / CT, HW / CT, NB * 8), 256>>>(x, w, out);
}